// round 13
// baseline (speedup 1.0000x reference)
#include <cuda_runtime.h>
#include <cuda_fp16.h>
#include <cstdint>

#define N_NODES 100000
#define N_EDGES 3200000
#define D 256

// ---------------------------------------------------------------------------
// Scratch (static device allocations only; zero-initialized at module load)
// ---------------------------------------------------------------------------
__device__ __half g_y[(size_t)N_NODES * D];   // y = x @ W^T (fp16, 51.2 MB)
__device__ int2   g_csr[N_EDGES];             // (col, val-bits) grouped by row
__device__ int    g_cnt[N_NODES];             // degree (re-zeroed by gather head)
__device__ int    g_off[N_NODES + 1];         // CSR row offsets
__device__ int    g_cur[N_NODES];             // fill cursors

__device__ __forceinline__ uint32_t smem_u32(const void* p) {
    uint32_t a;
    asm("{ .reg .u64 t; cvta.to.shared.u64 t, %1; cvt.u32.u64 %0, t; }"
        : "=r"(a) : "l"(p));
    return a;
}

#define LDM_X4(r, a)                                                        \
    asm volatile("ldmatrix.sync.aligned.m8n8.x4.shared.b16 "                \
                 "{%0,%1,%2,%3}, [%4];"                                     \
                 : "=r"((r)[0]), "=r"((r)[1]), "=r"((r)[2]), "=r"((r)[3])   \
                 : "r"(a))

#define MMA_F16(c, a, b0, b1)                                               \
    asm volatile("mma.sync.aligned.m16n8k16.row.col.f32.f16.f16.f32 "       \
                 "{%0,%1,%2,%3}, {%4,%5,%6,%7}, {%8,%9}, {%0,%1,%2,%3};"    \
                 : "+f"((c)[0]), "+f"((c)[1]), "+f"((c)[2]), "+f"((c)[3])   \
                 : "r"((a)[0]), "r"((a)[1]), "r"((a)[2]), "r"((a)[3]),      \
                   "r"(b0), "r"(b1))

// ---------------------------------------------------------------------------
// GEMM: g_y = fp16( x @ W^T )  single-pass fp16 mma.sync, double-buffered.
// CTA 128x128, K chunks of 32, 8 warps (2M x 4N), warp tile 64x32.
// Both A (x) and B (W) are loaded fp32 and converted in-register (no
// separate conv_w kernel).
// ---------------------------------------------------------------------------
#define APITCH 40
#define TILE_H (128 * APITCH)

__global__ void __launch_bounds__(256) gemm_mma_kernel(
    const float* __restrict__ x, const float* __restrict__ W)
{
    __shared__ __align__(16) __half sA[2][TILE_H];
    __shared__ __align__(16) __half sB[2][TILE_H];

    const int tid  = threadIdx.x;
    const int wid  = tid >> 5;
    const int lane = tid & 31;
    const int bm   = blockIdx.y * 128;
    const int bn   = blockIdx.x * 128;
    const int wm   = wid & 1;
    const int wn   = wid >> 1;

    float acc[4][4][4];
#pragma unroll
    for (int i = 0; i < 4; i++)
#pragma unroll
        for (int j = 0; j < 4; j++)
#pragma unroll
            for (int q = 0; q < 4; q++) acc[i][j][q] = 0.f;

    const int seg   = tid & 7;
    const int rbase = tid >> 3;

    float4 va[4], vb[4];

#define PREFETCH(kc) do {                                                     \
        const int gk = (kc) * 32 + seg * 4;                                   \
        _Pragma("unroll")                                                     \
        for (int t = 0; t < 4; t++) {                                         \
            int row  = t * 32 + rbase;                                        \
            int grow = bm + row;                                              \
            if (grow >= N_NODES) grow = N_NODES - 1;                          \
            va[t] = *reinterpret_cast<const float4*>(x + (size_t)grow * D + gk); \
            vb[t] = *reinterpret_cast<const float4*>(W + (size_t)(bn + row) * D + gk); \
        }                                                                     \
    } while (0)

    PREFETCH(0);

    for (int kc = 0; kc < 8; kc++) {
        const int buf = kc & 1;

#pragma unroll
        for (int t = 0; t < 4; t++) {
            int row = t * 32 + rbase;
            int off = row * APITCH + seg * 4;
            float4 v = va[t];
            __half2 a01 = __floats2half2_rn(v.x, v.y);
            __half2 a23 = __floats2half2_rn(v.z, v.w);
            *reinterpret_cast<uint2*>(&sA[buf][off]) =
                make_uint2(*reinterpret_cast<uint32_t*>(&a01),
                           *reinterpret_cast<uint32_t*>(&a23));
            float4 w = vb[t];
            __half2 b01 = __floats2half2_rn(w.x, w.y);
            __half2 b23 = __floats2half2_rn(w.z, w.w);
            *reinterpret_cast<uint2*>(&sB[buf][off]) =
                make_uint2(*reinterpret_cast<uint32_t*>(&b01),
                           *reinterpret_cast<uint32_t*>(&b23));
        }
        __syncthreads();

        if (kc < 7) PREFETCH(kc + 1);

        const uint32_t uA = smem_u32(sA[buf]);
        const uint32_t uB = smem_u32(sB[buf]);
        const int mat  = lane >> 3;
        const int lrow = lane & 7;
#pragma unroll
        for (int ks = 0; ks < 2; ks++) {
            const int kk = ks * 16;
            uint32_t af[4][4], bf[2][4];
#pragma unroll
            for (int mt = 0; mt < 4; mt++) {
                int r = wm * 64 + mt * 16 + (mat & 1) * 8 + lrow;
                int c = kk + (mat >> 1) * 8;
                LDM_X4(af[mt], uA + (uint32_t)(r * APITCH + c) * 2);
            }
#pragma unroll
            for (int p = 0; p < 2; p++) {
                int r = wn * 32 + p * 16 + (mat >> 1) * 8 + lrow;
                int c = kk + (mat & 1) * 8;
                LDM_X4(bf[p], uB + (uint32_t)(r * APITCH + c) * 2);
            }
#pragma unroll
            for (int mt = 0; mt < 4; mt++)
#pragma unroll
                for (int p = 0; p < 2; p++)
#pragma unroll
                    for (int h = 0; h < 2; h++) {
                        int nt = p * 2 + h;
                        MMA_F16(acc[mt][nt], af[mt], bf[p][h * 2], bf[p][h * 2 + 1]);
                    }
        }
        __syncthreads();
    }
#undef PREFETCH

    const int gr = lane >> 2;
    const int gc = (lane & 3) * 2;
#pragma unroll
    for (int mt = 0; mt < 4; mt++) {
        int m0 = bm + wm * 64 + mt * 16 + gr;
#pragma unroll
        for (int nt = 0; nt < 4; nt++) {
            int n = bn + wn * 32 + nt * 8 + gc;
            if (m0 < N_NODES) {
                __half2 h = __floats2half2_rn(acc[mt][nt][0], acc[mt][nt][1]);
                *reinterpret_cast<__half2*>(g_y + (size_t)m0 * D + n) = h;
            }
            if (m0 + 8 < N_NODES) {
                __half2 h = __floats2half2_rn(acc[mt][nt][2], acc[mt][nt][3]);
                *reinterpret_cast<__half2*>(g_y + (size_t)(m0 + 8) * D + n) = h;
            }
        }
    }
}

// ---------------------------------------------------------------------------
// CSR build:
//   hist: cnt[row]++  (REDG, no return)
//   scan_single: one-block exclusive scan of cnt -> off, cur  (~6us)
//   fill: csr[atomicAdd(cur[row],1)] = (col, val)
// ---------------------------------------------------------------------------
__global__ void hist_kernel(const int* __restrict__ edge_row) {
    int e = blockIdx.x * blockDim.x + threadIdx.x;
    if (e < N_EDGES) atomicAdd(&g_cnt[edge_row[e]], 1);
}

__global__ void __launch_bounds__(1024) scan_single_kernel() {
    __shared__ int s[1024];
    const int tid = threadIdx.x;
    const int CHUNK = (N_NODES + 1023) / 1024;   // 98
    int base = tid * CHUNK;
    int lim  = base + CHUNK;
    if (lim > N_NODES) lim = N_NODES;

    int sum = 0;
    for (int i = base; i < lim; i++) sum += g_cnt[i];
    s[tid] = sum;
    __syncthreads();
#pragma unroll
    for (int d = 1; d < 1024; d <<= 1) {
        int t = (tid >= d) ? s[tid - d] : 0;
        __syncthreads();
        s[tid] += t;
        __syncthreads();
    }
    int run = s[tid] - sum;          // exclusive prefix of this thread's chunk
    for (int i = base; i < lim; i++) {
        int c = g_cnt[i];
        g_off[i] = run;
        g_cur[i] = run;
        run += c;
    }
    if (tid == 0) g_off[N_NODES] = N_EDGES;
}

__global__ void fill_kernel(const int* __restrict__ edge_row,
                            const int* __restrict__ edge_col,
                            const float* __restrict__ edge_val) {
    int e = blockIdx.x * blockDim.x + threadIdx.x;
    if (e >= N_EDGES) return;
    int r = edge_row[e];
    int pos = atomicAdd(&g_cur[r], 1);
    g_csr[pos] = make_int2(edge_col[e], __float_as_int(edge_val[e]));
}

// ---------------------------------------------------------------------------
// Gather-aggregate: one warp per node.  out[r] = sum v_e * y[c_e] + b
// Head re-zeroes g_cnt for the next graph replay (replays fully serialize).
// ---------------------------------------------------------------------------
__global__ void __launch_bounds__(256) gather_kernel(
    const float* __restrict__ bias,
    float* __restrict__ out)
{
    int gtid = blockIdx.x * blockDim.x + threadIdx.x;
    if (gtid < N_NODES) g_cnt[gtid] = 0;    // cleanup for next replay

    int w    = gtid >> 5;
    int lane = threadIdx.x & 31;
    if (w >= N_NODES) return;

    int start = g_off[w];
    int end   = g_off[w + 1];

    float a[8];
#pragma unroll
    for (int j = 0; j < 8; j++) a[j] = 0.f;

    int e = start;
    for (; e + 4 <= end; e += 4) {
        int2 p0 = g_csr[e],     p1 = g_csr[e + 1];
        int2 p2 = g_csr[e + 2], p3 = g_csr[e + 3];
        uint4 q0 = reinterpret_cast<const uint4*>(g_y + (size_t)p0.x * D)[lane];
        uint4 q1 = reinterpret_cast<const uint4*>(g_y + (size_t)p1.x * D)[lane];
        uint4 q2 = reinterpret_cast<const uint4*>(g_y + (size_t)p2.x * D)[lane];
        uint4 q3 = reinterpret_cast<const uint4*>(g_y + (size_t)p3.x * D)[lane];
        float v0 = __int_as_float(p0.y), v1 = __int_as_float(p1.y);
        float v2 = __int_as_float(p2.y), v3 = __int_as_float(p3.y);
#define ACC_Q(q, v) do {                                                       \
        float2 f0 = __half22float2(*reinterpret_cast<const __half2*>(&(q).x)); \
        float2 f1 = __half22float2(*reinterpret_cast<const __half2*>(&(q).y)); \
        float2 f2 = __half22float2(*reinterpret_cast<const __half2*>(&(q).z)); \
        float2 f3 = __half22float2(*reinterpret_cast<const __half2*>(&(q).w)); \
        a[0] += (v) * f0.x; a[1] += (v) * f0.y;                                \
        a[2] += (v) * f1.x; a[3] += (v) * f1.y;                                \
        a[4] += (v) * f2.x; a[5] += (v) * f2.y;                                \
        a[6] += (v) * f3.x; a[7] += (v) * f3.y; } while (0)
        ACC_Q(q0, v0); ACC_Q(q1, v1); ACC_Q(q2, v2); ACC_Q(q3, v3);
    }
    for (; e < end; e++) {
        int2 p = g_csr[e];
        uint4 q = reinterpret_cast<const uint4*>(g_y + (size_t)p.x * D)[lane];
        float v = __int_as_float(p.y);
        ACC_Q(q, v);
    }
#undef ACC_Q

    const float4* bp = reinterpret_cast<const float4*>(bias + lane * 8);
    float4 b0 = bp[0], b1 = bp[1];
    float4 o0 = make_float4(a[0] + b0.x, a[1] + b0.y, a[2] + b0.z, a[3] + b0.w);
    float4 o1 = make_float4(a[4] + b1.x, a[5] + b1.y, a[6] + b1.z, a[7] + b1.w);
    float4* op = reinterpret_cast<float4*>(out + (size_t)w * D + lane * 8);
    op[0] = o0;
    op[1] = o1;
}

// ---------------------------------------------------------------------------
// Launch:
//   s2 (HIGH priority, issued first): hist -> scan_single -> fill
//   s1 (LOW priority):               gemm (W converted inline)
//   join -> gather (capture stream)
// ---------------------------------------------------------------------------
extern "C" void kernel_launch(void* const* d_in, const int* in_sizes, int n_in,
                              void* d_out, int out_size) {
    const float* x        = (const float*)d_in[0];
    const int*   edge_row = (const int*)  d_in[1];
    const int*   edge_col = (const int*)  d_in[2];
    const float* edge_val = (const float*)d_in[3];
    const float* W        = (const float*)d_in[4];
    const float* b        = (const float*)d_in[5];
    float*       out      = (float*)d_out;

    static cudaStream_t s1 = nullptr, s2 = nullptr;
    static cudaEvent_t evFork = nullptr, evEnd1 = nullptr, evEnd2 = nullptr;
    if (s1 == nullptr) {
        int prLo, prHi;
        cudaDeviceGetStreamPriorityRange(&prLo, &prHi);
        cudaStreamCreateWithPriority(&s1, cudaStreamNonBlocking, prLo);
        cudaStreamCreateWithPriority(&s2, cudaStreamNonBlocking, prHi);
        cudaEventCreateWithFlags(&evFork, cudaEventDisableTiming);
        cudaEventCreateWithFlags(&evEnd1, cudaEventDisableTiming);
        cudaEventCreateWithFlags(&evEnd2, cudaEventDisableTiming);
    }

    // fork from capture stream
    cudaEventRecord(evFork, 0);
    cudaStreamWaitEvent(s1, evFork, 0);
    cudaStreamWaitEvent(s2, evFork, 0);

    // Branch B (s2, high priority): CSR build
    hist_kernel<<<(N_EDGES + 255) / 256, 256, 0, s2>>>(edge_row);
    scan_single_kernel<<<1, 1024, 0, s2>>>();
    fill_kernel<<<(N_EDGES + 255) / 256, 256, 0, s2>>>(edge_row, edge_col, edge_val);

    // Branch A (s1, low priority): GEMM
    {
        dim3 grid(D / 128, (N_NODES + 127) / 128);   // (2, 782)
        gemm_mma_kernel<<<grid, 256, 0, s1>>>(x, W);
    }

    // join
    cudaEventRecord(evEnd1, s1);
    cudaEventRecord(evEnd2, s2);
    cudaStreamWaitEvent(0, evEnd1, 0);
    cudaStreamWaitEvent(0, evEnd2, 0);

    // Gather-aggregate + bias -> out
    gather_kernel<<<(N_NODES + 7) / 8, 256>>>(b, out);
}

// round 14
// speedup vs baseline: 1.7569x; 1.7569x over previous
#include <cuda_runtime.h>
#include <cuda_fp16.h>
#include <cstdint>

#define N_NODES 100000
#define N_EDGES 3200000
#define D 256
#define SCAN_B 1024
#define NB ((N_NODES + SCAN_B - 1) / SCAN_B)   // 98

// ---------------------------------------------------------------------------
// Scratch (static device allocations only; zero-initialized at module load)
// ---------------------------------------------------------------------------
__device__ __half g_y[(size_t)N_NODES * D];   // y = x @ W^T (fp16, 51.2 MB)
__device__ __half g_Wh[D * D];                // W as fp16
__device__ int2   g_csr[N_EDGES];             // (col, val-bits) grouped by row
__device__ int    g_cnt[N_NODES];             // degree (re-zeroed by gather head)
__device__ int    g_off[N_NODES + 1];         // CSR row offsets
__device__ int    g_cur[N_NODES];             // fill cursors
__device__ int    g_bsum[NB];
__device__ int    g_boff[NB];

__device__ __forceinline__ uint32_t smem_u32(const void* p) {
    uint32_t a;
    asm("{ .reg .u64 t; cvta.to.shared.u64 t, %1; cvt.u32.u64 %0, t; }"
        : "=r"(a) : "l"(p));
    return a;
}

#define LDM_X4(r, a)                                                        \
    asm volatile("ldmatrix.sync.aligned.m8n8.x4.shared.b16 "                \
                 "{%0,%1,%2,%3}, [%4];"                                     \
                 : "=r"((r)[0]), "=r"((r)[1]), "=r"((r)[2]), "=r"((r)[3])   \
                 : "r"(a))

#define MMA_F16(c, a, b0, b1)                                               \
    asm volatile("mma.sync.aligned.m16n8k16.row.col.f32.f16.f16.f32 "       \
                 "{%0,%1,%2,%3}, {%4,%5,%6,%7}, {%8,%9}, {%0,%1,%2,%3};"    \
                 : "+f"((c)[0]), "+f"((c)[1]), "+f"((c)[2]), "+f"((c)[3])   \
                 : "r"((a)[0]), "r"((a)[1]), "r"((a)[2]), "r"((a)[3]),      \
                   "r"(b0), "r"(b1))

// ---------------------------------------------------------------------------
// W -> fp16 precompute
// ---------------------------------------------------------------------------
__global__ void conv_w_kernel(const float* __restrict__ W) {
    int i = blockIdx.x * blockDim.x + threadIdx.x;
    float4 v = reinterpret_cast<const float4*>(W)[i];
    __half2 h01 = __floats2half2_rn(v.x, v.y);
    __half2 h23 = __floats2half2_rn(v.z, v.w);
    reinterpret_cast<uint2*>(g_Wh)[i] =
        make_uint2(*reinterpret_cast<uint32_t*>(&h01), *reinterpret_cast<uint32_t*>(&h23));
}

// ---------------------------------------------------------------------------
// GEMM: g_y = fp16( x @ W^T )  single-pass fp16 mma.sync, double-buffered.
// CTA 128x128, K chunks of 32, 8 warps (2M x 4N), warp tile 64x32.
// ---------------------------------------------------------------------------
#define APITCH 40
#define TILE_H (128 * APITCH)

__global__ void __launch_bounds__(256) gemm_mma_kernel(
    const float* __restrict__ x)
{
    __shared__ __align__(16) __half sA[2][TILE_H];
    __shared__ __align__(16) __half sB[2][TILE_H];

    const int tid  = threadIdx.x;
    const int wid  = tid >> 5;
    const int lane = tid & 31;
    const int bm   = blockIdx.y * 128;
    const int bn   = blockIdx.x * 128;
    const int wm   = wid & 1;
    const int wn   = wid >> 1;

    float acc[4][4][4];
#pragma unroll
    for (int i = 0; i < 4; i++)
#pragma unroll
        for (int j = 0; j < 4; j++)
#pragma unroll
            for (int q = 0; q < 4; q++) acc[i][j][q] = 0.f;

    const int seg   = tid & 7;
    const int rbase = tid >> 3;

    float4 va[4];
    uint2  vb[4];

#define PREFETCH(kc) do {                                                     \
        const int gk = (kc) * 32 + seg * 4;                                   \
        _Pragma("unroll")                                                     \
        for (int t = 0; t < 4; t++) {                                         \
            int row  = t * 32 + rbase;                                        \
            int grow = bm + row;                                              \
            if (grow >= N_NODES) grow = N_NODES - 1;                          \
            va[t] = *reinterpret_cast<const float4*>(x + (size_t)grow * D + gk); \
            vb[t] = reinterpret_cast<const uint2*>(g_Wh)[((size_t)(bn + row) * D + gk) >> 2]; \
        }                                                                     \
    } while (0)

    PREFETCH(0);

    for (int kc = 0; kc < 8; kc++) {
        const int buf = kc & 1;

#pragma unroll
        for (int t = 0; t < 4; t++) {
            int row = t * 32 + rbase;
            int off = row * APITCH + seg * 4;
            float4 v = va[t];
            __half2 h01 = __floats2half2_rn(v.x, v.y);
            __half2 h23 = __floats2half2_rn(v.z, v.w);
            *reinterpret_cast<uint2*>(&sA[buf][off]) =
                make_uint2(*reinterpret_cast<uint32_t*>(&h01),
                           *reinterpret_cast<uint32_t*>(&h23));
            *reinterpret_cast<uint2*>(&sB[buf][off]) = vb[t];
        }
        __syncthreads();

        if (kc < 7) PREFETCH(kc + 1);

        const uint32_t uA = smem_u32(sA[buf]);
        const uint32_t uB = smem_u32(sB[buf]);
        const int mat  = lane >> 3;
        const int lrow = lane & 7;
#pragma unroll
        for (int ks = 0; ks < 2; ks++) {
            const int kk = ks * 16;
            uint32_t af[4][4], bf[2][4];
#pragma unroll
            for (int mt = 0; mt < 4; mt++) {
                int r = wm * 64 + mt * 16 + (mat & 1) * 8 + lrow;
                int c = kk + (mat >> 1) * 8;
                LDM_X4(af[mt], uA + (uint32_t)(r * APITCH + c) * 2);
            }
#pragma unroll
            for (int p = 0; p < 2; p++) {
                int r = wn * 32 + p * 16 + (mat >> 1) * 8 + lrow;
                int c = kk + (mat & 1) * 8;
                LDM_X4(bf[p], uB + (uint32_t)(r * APITCH + c) * 2);
            }
#pragma unroll
            for (int mt = 0; mt < 4; mt++)
#pragma unroll
                for (int p = 0; p < 2; p++)
#pragma unroll
                    for (int h = 0; h < 2; h++) {
                        int nt = p * 2 + h;
                        MMA_F16(acc[mt][nt], af[mt], bf[p][h * 2], bf[p][h * 2 + 1]);
                    }
        }
        __syncthreads();
    }
#undef PREFETCH

    const int gr = lane >> 2;
    const int gc = (lane & 3) * 2;
#pragma unroll
    for (int mt = 0; mt < 4; mt++) {
        int m0 = bm + wm * 64 + mt * 16 + gr;
#pragma unroll
        for (int nt = 0; nt < 4; nt++) {
            int n = bn + wn * 32 + nt * 8 + gc;
            if (m0 < N_NODES) {
                __half2 h = __floats2half2_rn(acc[mt][nt][0], acc[mt][nt][1]);
                *reinterpret_cast<__half2*>(g_y + (size_t)m0 * D + n) = h;
            }
            if (m0 + 8 < N_NODES) {
                __half2 h = __floats2half2_rn(acc[mt][nt][2], acc[mt][nt][3]);
                *reinterpret_cast<__half2*>(g_y + (size_t)(m0 + 8) * D + n) = h;
            }
        }
    }
}

// ---------------------------------------------------------------------------
// CSR construction (R10-proven: hist -> scan1/2/3 -> fill)
// g_cnt starts zero (module load) and is re-zeroed by the gather head each
// call, so no zero kernel is needed on the critical path.
// ---------------------------------------------------------------------------
__global__ void hist_kernel(const int* __restrict__ edge_row) {
    int e = blockIdx.x * blockDim.x + threadIdx.x;
    if (e < N_EDGES) atomicAdd(&g_cnt[edge_row[e]], 1);
}
__global__ void scan1_kernel() {
    __shared__ int s[SCAN_B];
    int i = blockIdx.x * SCAN_B + threadIdx.x;
    int v = (i < N_NODES) ? g_cnt[i] : 0;
    s[threadIdx.x] = v;
    __syncthreads();
#pragma unroll
    for (int d = 1; d < SCAN_B; d <<= 1) {
        int t = (threadIdx.x >= d) ? s[threadIdx.x - d] : 0;
        __syncthreads();
        s[threadIdx.x] += t;
        __syncthreads();
    }
    if (i < N_NODES) g_off[i] = s[threadIdx.x] - v;
    if (threadIdx.x == SCAN_B - 1) g_bsum[blockIdx.x] = s[SCAN_B - 1];
}
__global__ void scan2_kernel() {
    __shared__ int s[128];
    int v = (threadIdx.x < NB) ? g_bsum[threadIdx.x] : 0;
    s[threadIdx.x] = v;
    __syncthreads();
#pragma unroll
    for (int d = 1; d < 128; d <<= 1) {
        int t = (threadIdx.x >= d) ? s[threadIdx.x - d] : 0;
        __syncthreads();
        s[threadIdx.x] += t;
        __syncthreads();
    }
    if (threadIdx.x < NB) g_boff[threadIdx.x] = s[threadIdx.x] - v;
}
__global__ void scan3_kernel() {
    int i = blockIdx.x * SCAN_B + threadIdx.x;
    if (i < N_NODES) {
        int o = g_off[i] + g_boff[blockIdx.x];
        g_off[i] = o;
        g_cur[i] = o;
    }
    if (i == 0) g_off[N_NODES] = N_EDGES;
}
__global__ void fill_kernel(const int* __restrict__ edge_row,
                            const int* __restrict__ edge_col,
                            const float* __restrict__ edge_val) {
    int e = blockIdx.x * blockDim.x + threadIdx.x;
    if (e >= N_EDGES) return;
    int r = edge_row[e];
    int pos = atomicAdd(&g_cur[r], 1);
    g_csr[pos] = make_int2(edge_col[e], __float_as_int(edge_val[e]));
}

// ---------------------------------------------------------------------------
// Gather-aggregate: one warp per node.  out[r] = sum v_e * y[c_e] + b
// Head re-zeroes g_cnt for the next graph replay (replays fully serialize).
// ---------------------------------------------------------------------------
__global__ void __launch_bounds__(256) gather_kernel(
    const float* __restrict__ bias,
    float* __restrict__ out)
{
    int gtid = blockIdx.x * blockDim.x + threadIdx.x;
    if (gtid < N_NODES) g_cnt[gtid] = 0;    // cleanup for next replay

    int w    = gtid >> 5;
    int lane = threadIdx.x & 31;
    if (w >= N_NODES) return;

    int start = g_off[w];
    int end   = g_off[w + 1];

    float a[8];
#pragma unroll
    for (int j = 0; j < 8; j++) a[j] = 0.f;

    int e = start;
    for (; e + 4 <= end; e += 4) {
        int2 p0 = g_csr[e],     p1 = g_csr[e + 1];
        int2 p2 = g_csr[e + 2], p3 = g_csr[e + 3];
        uint4 q0 = reinterpret_cast<const uint4*>(g_y + (size_t)p0.x * D)[lane];
        uint4 q1 = reinterpret_cast<const uint4*>(g_y + (size_t)p1.x * D)[lane];
        uint4 q2 = reinterpret_cast<const uint4*>(g_y + (size_t)p2.x * D)[lane];
        uint4 q3 = reinterpret_cast<const uint4*>(g_y + (size_t)p3.x * D)[lane];
        float v0 = __int_as_float(p0.y), v1 = __int_as_float(p1.y);
        float v2 = __int_as_float(p2.y), v3 = __int_as_float(p3.y);
#define ACC_Q(q, v) do {                                                       \
        float2 f0 = __half22float2(*reinterpret_cast<const __half2*>(&(q).x)); \
        float2 f1 = __half22float2(*reinterpret_cast<const __half2*>(&(q).y)); \
        float2 f2 = __half22float2(*reinterpret_cast<const __half2*>(&(q).z)); \
        float2 f3 = __half22float2(*reinterpret_cast<const __half2*>(&(q).w)); \
        a[0] += (v) * f0.x; a[1] += (v) * f0.y;                                \
        a[2] += (v) * f1.x; a[3] += (v) * f1.y;                                \
        a[4] += (v) * f2.x; a[5] += (v) * f2.y;                                \
        a[6] += (v) * f3.x; a[7] += (v) * f3.y; } while (0)
        ACC_Q(q0, v0); ACC_Q(q1, v1); ACC_Q(q2, v2); ACC_Q(q3, v3);
    }
    for (; e < end; e++) {
        int2 p = g_csr[e];
        uint4 q = reinterpret_cast<const uint4*>(g_y + (size_t)p.x * D)[lane];
        float v = __int_as_float(p.y);
        ACC_Q(q, v);
    }
#undef ACC_Q

    const float4* bp = reinterpret_cast<const float4*>(bias + lane * 8);
    float4 b0 = bp[0], b1 = bp[1];
    float4 o0 = make_float4(a[0] + b0.x, a[1] + b0.y, a[2] + b0.z, a[3] + b0.w);
    float4 o1 = make_float4(a[4] + b1.x, a[5] + b1.y, a[6] + b1.z, a[7] + b1.w);
    float4* op = reinterpret_cast<float4*>(out + (size_t)w * D + lane * 8);
    op[0] = o0;
    op[1] = o1;
}

// ---------------------------------------------------------------------------
// Launch:
//   s2 (HIGH priority, issued first): hist -> scan1/2/3 -> fill
//   s1 (LOW priority):               conv_w -> gemm
//   join -> gather (capture stream)
// ---------------------------------------------------------------------------
extern "C" void kernel_launch(void* const* d_in, const int* in_sizes, int n_in,
                              void* d_out, int out_size) {
    const float* x        = (const float*)d_in[0];
    const int*   edge_row = (const int*)  d_in[1];
    const int*   edge_col = (const int*)  d_in[2];
    const float* edge_val = (const float*)d_in[3];
    const float* W        = (const float*)d_in[4];
    const float* b        = (const float*)d_in[5];
    float*       out      = (float*)d_out;

    static cudaStream_t s1 = nullptr, s2 = nullptr;
    static cudaEvent_t evFork = nullptr, evEnd1 = nullptr, evEnd2 = nullptr;
    if (s1 == nullptr) {
        int prLo, prHi;
        cudaDeviceGetStreamPriorityRange(&prLo, &prHi);
        cudaStreamCreateWithPriority(&s1, cudaStreamNonBlocking, prLo);
        cudaStreamCreateWithPriority(&s2, cudaStreamNonBlocking, prHi);
        cudaEventCreateWithFlags(&evFork, cudaEventDisableTiming);
        cudaEventCreateWithFlags(&evEnd1, cudaEventDisableTiming);
        cudaEventCreateWithFlags(&evEnd2, cudaEventDisableTiming);
    }

    // fork from capture stream
    cudaEventRecord(evFork, 0);
    cudaStreamWaitEvent(s1, evFork, 0);
    cudaStreamWaitEvent(s2, evFork, 0);

    // Branch B (s2, high priority): CSR build
    hist_kernel<<<(N_EDGES + 255) / 256, 256, 0, s2>>>(edge_row);
    scan1_kernel<<<NB, SCAN_B, 0, s2>>>();
    scan2_kernel<<<1, 128, 0, s2>>>();
    scan3_kernel<<<NB, SCAN_B, 0, s2>>>();
    fill_kernel<<<(N_EDGES + 255) / 256, 256, 0, s2>>>(edge_row, edge_col, edge_val);

    // Branch A (s1, low priority): W -> fp16, then GEMM
    conv_w_kernel<<<(D * D / 4) / 256, 256, 0, s1>>>(W);
    {
        dim3 grid(D / 128, (N_NODES + 127) / 128);   // (2, 782)
        gemm_mma_kernel<<<grid, 256, 0, s1>>>(x);
    }

    // join
    cudaEventRecord(evEnd1, s1);
    cudaEventRecord(evEnd2, s2);
    cudaStreamWaitEvent(0, evEnd1, 0);
    cudaStreamWaitEvent(0, evEnd2, 0);

    // Gather-aggregate + bias -> out
    gather_kernel<<<(N_NODES + 7) / 8, 256>>>(b, out);
}